// round 11
// baseline (speedup 1.0000x reference)
#include <cuda_runtime.h>
#include <cuda_fp16.h>
#include <stdint.h>
#include <math.h>

#define HEADS 16
#define DH    64
#define BATCH 8
#define SEQ   512
#define DMODEL 1024
#define INNER 1024            // HEADS*DH
#define QKV_N 3072            // 3*INNER
#define NTOK  4096            // BATCH*SEQ

// Scratch (device globals: allocation-free, graph-capture safe)
__device__ __half g_xh[(size_t)NTOK * DMODEL];               // 8 MB
__device__ __half g_qkvh[(size_t)NTOK * QKV_N];              // 24 MB
__device__ float  g_dots[(size_t)BATCH * HEADS * SEQ * SEQ]; // 128 MB
__device__ __half g_attnh[(size_t)BATCH * HEADS * SEQ * SEQ];// 64 MB
__device__ __half g_avh[(size_t)NTOK * INNER];               // 8 MB
__device__ __half g_wqkvT[(size_t)QKV_N * DMODEL];           // 6 MB [n][k]
__device__ __half g_woutT[(size_t)DMODEL * INNER];           // 2 MB [n][k]
__device__ __half g_vT[(size_t)BATCH * HEADS * DH * SEQ];    // 8 MB [b][h][d][j]

// ---------------------------------------------------------------------------
__device__ __forceinline__ void mma16(float* c, const uint32_t* a, const uint32_t* b) {
    asm volatile(
        "mma.sync.aligned.m16n8k16.row.col.f32.f16.f16.f32 "
        "{%0,%1,%2,%3}, {%4,%5,%6,%7}, {%8,%9}, {%0,%1,%2,%3};"
        : "+f"(c[0]), "+f"(c[1]), "+f"(c[2]), "+f"(c[3])
        : "r"(a[0]), "r"(a[1]), "r"(a[2]), "r"(a[3]),
          "r"(b[0]), "r"(b[1]));
}

__device__ __forceinline__ void ldsm_x4(uint32_t* r, const __half* p) {
    uint32_t addr = (uint32_t)__cvta_generic_to_shared(p);
    asm volatile(
        "ldmatrix.sync.aligned.m8n8.x4.shared.b16 {%0,%1,%2,%3}, [%4];"
        : "=r"(r[0]), "=r"(r[1]), "=r"(r[2]), "=r"(r[3]) : "r"(addr));
}

__device__ __forceinline__ void cp16(uint32_t smem_dst, const void* gsrc) {
    asm volatile("cp.async.cg.shared.global [%0], [%1], 16;"
                 :: "r"(smem_dst), "l"(gsrc));
}

// ---------------------------------------------------------------------------
// Prep kernels
// ---------------------------------------------------------------------------
__global__ void __launch_bounds__(256) x_cvt(
    const float* __restrict__ in, __half* __restrict__ out)
{
    size_t i = ((size_t)blockIdx.x * 256 + threadIdx.x) * 8;
    float4 a = *reinterpret_cast<const float4*>(in + i);
    float4 b = *reinterpret_cast<const float4*>(in + i + 4);
    __half2 h0 = __floats2half2_rn(a.x, a.y);
    __half2 h1 = __floats2half2_rn(a.z, a.w);
    __half2 h2 = __floats2half2_rn(b.x, b.y);
    __half2 h3 = __floats2half2_rn(b.z, b.w);
    uint4 u;
    u.x = *reinterpret_cast<uint32_t*>(&h0);
    u.y = *reinterpret_cast<uint32_t*>(&h1);
    u.z = *reinterpret_cast<uint32_t*>(&h2);
    u.w = *reinterpret_cast<uint32_t*>(&h3);
    *reinterpret_cast<uint4*>(out + i) = u;
}

__global__ void __launch_bounds__(256) transpose_cvt(
    const float* __restrict__ in, __half* __restrict__ out, int K, int N)
{
    __shared__ float tile[32][33];
    const int k0 = blockIdx.y * 32, n0 = blockIdx.x * 32;
    const int tx = threadIdx.x & 31, ty = threadIdx.x >> 5;
    #pragma unroll
    for (int t = 0; t < 4; t++)
        tile[ty + t * 8][tx] = in[(size_t)(k0 + ty + t * 8) * N + n0 + tx];
    __syncthreads();
    #pragma unroll
    for (int t = 0; t < 4; t++)
        out[(size_t)(n0 + ty + t * 8) * K + k0 + tx] =
            __float2half_rn(tile[tx][ty + t * 8]);
}

__global__ void __launch_bounds__(256) v_transpose(
    const __half* __restrict__ qkvh, __half* __restrict__ vT)
{
    __shared__ __half tile[32][34];
    const int bh = blockIdx.z, b = bh >> 4, h = bh & 15;
    const int j0 = blockIdx.x * 32, d0 = blockIdx.y * 32;
    const int tx = threadIdx.x & 31, ty = threadIdx.x >> 5;
    const __half* src = qkvh + (size_t)b * SEQ * QKV_N + 2 * INNER + h * DH;
    #pragma unroll
    for (int t = 0; t < 4; t++)
        tile[ty + t * 8][tx] = src[(size_t)(j0 + ty + t * 8) * QKV_N + d0 + tx];
    __syncthreads();
    __half* dst = vT + (size_t)bh * DH * SEQ;
    #pragma unroll
    for (int t = 0; t < 4; t++)
        dst[(size_t)(d0 + ty + t * 8) * SEQ + j0 + tx] = tile[tx][ty + t * 8];
}

// ---------------------------------------------------------------------------
// fp16 tensor-core GEMM: cp.async 3-stage pipeline + ldmatrix fragments.
// __launch_bounds__(256, 3): 85-reg cap -> 3 CTAs/SM (register-limited fix).
// MODE 0: QKV  qkvh = xh @ wqkvT        MODE 1: OUT out(f32) = avh @ woutT + b
// MODE 2: AV   avh = attnh @ vT (per bh) MODE 3: DOTS dots(f32)=alpha*Qh@Kh^T
// ---------------------------------------------------------------------------
template<int MODE, int BM, int BN, int KTOT>
__global__ void __launch_bounds__(256, 3) hgemm(
    const __half* __restrict__ gA, const __half* __restrict__ gB,
    const float* __restrict__ bias, void* __restrict__ gC)
{
    constexpr bool CHALF = (MODE == 0 || MODE == 2);
    constexpr int MI = BM / 64;
    constexpr int NP = BN / 32;
    constexpr int LK = 40;
    constexpr int S  = 3;
    constexpr int T  = KTOT / 32;
    constexpr int NLDA = BM / 64;
    constexpr int NLDB = BN / 64;

    __shared__ __align__(16) __half sA[S][BM * LK];
    __shared__ __align__(16) __half sB[S][BN * LK];

    const int tid  = threadIdx.x;
    const int row0 = blockIdx.y * BM;
    const int col0 = blockIdx.x * BN;

    const __half* A;
    const __half* B;
    float*  Cf = nullptr;
    __half* Ch = nullptr;
    int lda, ldb, ldc;
    float alpha = 1.0f;

    if (MODE == 0) {
        A = gA; lda = DMODEL; B = gB; ldb = DMODEL;
        Ch = (__half*)gC; ldc = QKV_N;
    } else if (MODE == 1) {
        A = gA; lda = DMODEL; B = gB; ldb = DMODEL;
        Cf = (float*)gC; ldc = DMODEL;
    } else if (MODE == 2) {
        const int bh = blockIdx.z, b = bh >> 4, h = bh & 15;
        A = gA + (size_t)bh * SEQ * SEQ;            lda = SEQ;
        B = gB + (size_t)bh * DH * SEQ;             ldb = SEQ;
        Ch = (__half*)gC + (size_t)b * SEQ * INNER + (size_t)h * DH; ldc = INNER;
    } else {
        const int bh = blockIdx.z, b = bh >> 4, h = bh & 15;
        A = gA + (size_t)b * SEQ * QKV_N + (size_t)h * DH;          lda = QKV_N;
        B = gB + (size_t)b * SEQ * QKV_N + INNER + (size_t)h * DH;  ldb = QKV_N;
        Cf = (float*)gC + (size_t)bh * SEQ * SEQ;                   ldc = SEQ;
        alpha = 0.125f;
    }

    const int warp = tid >> 5, lane = tid & 31;
    const int wm = warp >> 1, wn = warp & 1;
    const int g = lane >> 2, t4 = lane & 3;
    const int lmRow = lane & 15;
    const int lmK8  = (lane >> 4) * 8;

    const int hR = tid >> 2;
    const int hC = tid & 3;

    const uint32_t sA0 = (uint32_t)__cvta_generic_to_shared(&sA[0][0]);
    const uint32_t sB0 = (uint32_t)__cvta_generic_to_shared(&sB[0][0]);

    auto cpStage = [&](int kt, int st) {
        const int k0 = kt * 32;
        #pragma unroll
        for (int p = 0; p < NLDA; p++) {
            int r = hR + p * 64;
            cp16(sA0 + (uint32_t)((st * BM + r) * LK + hC * 8) * 2,
                 &A[(size_t)(row0 + r) * lda + k0 + hC * 8]);
        }
        #pragma unroll
        for (int p = 0; p < NLDB; p++) {
            int r = hR + p * 64;
            cp16(sB0 + (uint32_t)((st * BN + r) * LK + hC * 8) * 2,
                 &B[(size_t)(col0 + r) * ldb + k0 + hC * 8]);
        }
    };

    float acc[MI][NP * 2][4] = {};

    #pragma unroll
    for (int s = 0; s < S - 1; s++) {
        if (s < T) cpStage(s, s);
        asm volatile("cp.async.commit_group;");
    }

    for (int t = 0; t < T; t++) {
        asm volatile("cp.async.wait_group 1;");
        __syncthreads();

        const int nt = t + S - 1;
        if (nt < T) cpStage(nt, nt % S);
        asm volatile("cp.async.commit_group;");

        const __half* cA = sA[t % S];
        const __half* cB = sB[t % S];

        #pragma unroll
        for (int kk = 0; kk < 2; kk++) {
            const int kc = kk * 16 + lmK8;
            uint32_t af[MI][4];
            #pragma unroll
            for (int mi = 0; mi < MI; mi++) {
                int r = wm * (BM / 4) + mi * 16 + lmRow;
                ldsm_x4(af[mi], &cA[r * LK + kc]);
            }
            uint32_t bfp[NP][4];
            #pragma unroll
            for (int p = 0; p < NP; p++) {
                int c = wn * (BN / 2) + p * 16 + lmRow;
                ldsm_x4(bfp[p], &cB[c * LK + kc]);
            }
            #pragma unroll
            for (int mi = 0; mi < MI; mi++)
                #pragma unroll
                for (int p = 0; p < NP; p++) {
                    uint32_t b0[2] = { bfp[p][0], bfp[p][2] };
                    uint32_t b1[2] = { bfp[p][1], bfp[p][3] };
                    mma16(acc[mi][2 * p],     af[mi], b0);
                    mma16(acc[mi][2 * p + 1], af[mi], b1);
                }
        }
    }

    #pragma unroll
    for (int mi = 0; mi < MI; mi++) {
        int r = row0 + wm * (BM / 4) + mi * 16 + g;
        #pragma unroll
        for (int ni = 0; ni < NP * 2; ni++) {
            int c = col0 + wn * (BN / 2) + (ni >> 1) * 16 + (ni & 1) * 8 + 2 * t4;
            float* a = acc[mi][ni];
            if (CHALF) {
                __half2 hv0 = __floats2half2_rn(a[0], a[1]);
                __half2 hv1 = __floats2half2_rn(a[2], a[3]);
                *reinterpret_cast<__half2*>(&Ch[(size_t)r * ldc + c]) = hv0;
                *reinterpret_cast<__half2*>(&Ch[(size_t)(r + 8) * ldc + c]) = hv1;
            } else {
                float b0 = 0.f, b1 = 0.f;
                if (MODE == 1) { b0 = bias[c]; b1 = bias[c + 1]; }
                float2 v0, v1;
                v0.x = a[0] * alpha + b0; v0.y = a[1] * alpha + b1;
                v1.x = a[2] * alpha + b0; v1.y = a[3] * alpha + b1;
                *reinterpret_cast<float2*>(&Cf[(size_t)r * ldc + c]) = v0;
                *reinterpret_cast<float2*>(&Cf[(size_t)(r + 8) * ldc + c]) = v1;
            }
        }
    }
}

// ---------------------------------------------------------------------------
// Fused softmax + head-mix + LayerNorm (proven R7 version).
// ---------------------------------------------------------------------------
__global__ void __launch_bounds__(512) softmax_mix_ln_kernel(
    const float* __restrict__ dots, __half* __restrict__ attnh,
    const float* __restrict__ W,
    const float* __restrict__ gamma, const float* __restrict__ beta)
{
    const int bi = blockIdx.x;
    const int b  = bi >> 9;
    const int i  = bi & 511;

    __shared__ float sc[HEADS][SEQ];
    __shared__ float wmat[HEADS][HEADS];
    __shared__ float sg[HEADS], sb[HEADS];

    const int tid = threadIdx.x;
    if (tid < 256) wmat[tid >> 4][tid & 15] = W[tid];
    if (tid < HEADS) { sg[tid] = gamma[tid]; sb[tid] = beta[tid]; }

    #pragma unroll
    for (int t = 0; t < 4; t++) {
        int idx = tid + t * 512;
        int h   = idx >> 7;
        int j4  = idx & 127;
        float4 v = *reinterpret_cast<const float4*>(
            &dots[((size_t)(b * HEADS + h) * SEQ + i) * SEQ + j4 * 4]);
        *reinterpret_cast<float4*>(&sc[h][j4 * 4]) = v;
    }
    __syncthreads();

    const int h = tid >> 5, lane = tid & 31;
    {
        float mx = -1e30f;
        #pragma unroll
        for (int t = 0; t < 16; t++) mx = fmaxf(mx, sc[h][lane + t * 32]);
        #pragma unroll
        for (int o = 16; o > 0; o >>= 1)
            mx = fmaxf(mx, __shfl_xor_sync(0xffffffffu, mx, o));
        float s = 0.f;
        #pragma unroll
        for (int t = 0; t < 16; t++) {
            float e = __expf(sc[h][lane + t * 32] - mx);
            sc[h][lane + t * 32] = e;
            s += e;
        }
        #pragma unroll
        for (int o = 16; o > 0; o >>= 1)
            s += __shfl_xor_sync(0xffffffffu, s, o);
        float inv = 1.f / s;
        #pragma unroll
        for (int t = 0; t < 16; t++) sc[h][lane + t * 32] *= inv;
    }
    __syncthreads();

    {
        const int j = tid;
        float a[HEADS];
        #pragma unroll
        for (int hh = 0; hh < HEADS; hh++) a[hh] = sc[hh][j];
        float mixed[HEADS];
        #pragma unroll
        for (int gg = 0; gg < HEADS; gg++) {
            float s = 0.f;
            #pragma unroll
            for (int hh = 0; hh < HEADS; hh++) s = fmaf(a[hh], wmat[hh][gg], s);
            mixed[gg] = s;
        }
        float mean = 0.f;
        #pragma unroll
        for (int gg = 0; gg < HEADS; gg++) mean += mixed[gg];
        mean *= (1.f / HEADS);
        float var = 0.f;
        #pragma unroll
        for (int gg = 0; gg < HEADS; gg++) {
            float d = mixed[gg] - mean;
            var = fmaf(d, d, var);
        }
        var *= (1.f / HEADS);
        float inv = rsqrtf(var + 1e-3f);
        #pragma unroll
        for (int gg = 0; gg < HEADS; gg++) {
            float y = (mixed[gg] - mean) * inv * sg[gg] + sb[gg];
            attnh[((size_t)(b * HEADS + gg) * SEQ + i) * SEQ + j] =
                __float2half_rn(y);
        }
    }
}

// ---------------------------------------------------------------------------
extern "C" void kernel_launch(void* const* d_in, const int* in_sizes, int n_in,
                              void* d_out, int out_size)
{
    const float* x        = (const float*)d_in[0];
    const float* w_qkv    = (const float*)d_in[1];
    const float* reattn_w = (const float*)d_in[2];
    const float* ln_gamma = (const float*)d_in[3];
    const float* ln_beta  = (const float*)d_in[4];
    const float* w_out    = (const float*)d_in[5];
    const float* b_out    = (const float*)d_in[6];
    float* out = (float*)d_out;

    __half *xh = nullptr, *qkvh = nullptr, *attnh = nullptr, *avh = nullptr;
    __half *wqkvT = nullptr, *woutT = nullptr, *vT = nullptr;
    float *dots = nullptr;
    cudaGetSymbolAddress((void**)&xh,    g_xh);
    cudaGetSymbolAddress((void**)&qkvh,  g_qkvh);
    cudaGetSymbolAddress((void**)&dots,  g_dots);
    cudaGetSymbolAddress((void**)&attnh, g_attnh);
    cudaGetSymbolAddress((void**)&avh,   g_avh);
    cudaGetSymbolAddress((void**)&wqkvT, g_wqkvT);
    cudaGetSymbolAddress((void**)&woutT, g_woutT);
    cudaGetSymbolAddress((void**)&vT,    g_vT);

    dim3 blk(256);

    // 0) prep
    x_cvt<<<(NTOK * DMODEL) / (256 * 8), blk>>>(x, xh);
    transpose_cvt<<<dim3(QKV_N / 32, DMODEL / 32), blk>>>(w_qkv, wqkvT, DMODEL, QKV_N);
    transpose_cvt<<<dim3(DMODEL / 32, DMODEL / 32), blk>>>(w_out, woutT, DMODEL, DMODEL);

    // 1) QKV projection -> fp16
    hgemm<0, 128, 128, 1024><<<dim3(QKV_N / 128, NTOK / 128), blk>>>(
        xh, wqkvT, nullptr, qkvh);

    // 1b) V transpose
    v_transpose<<<dim3(SEQ / 32, DH / 32, BATCH * HEADS), blk>>>(qkvh, vT);

    // 2) dots -> fp32
    hgemm<3, 128, 128, 64><<<dim3(SEQ / 128, SEQ / 128, BATCH * HEADS), blk>>>(
        qkvh, qkvh, nullptr, dots);

    // 3) fused softmax + head mix + LayerNorm -> fp16
    softmax_mix_ln_kernel<<<BATCH * SEQ, 512>>>(dots, attnh, reattn_w, ln_gamma, ln_beta);

    // 4) AV -> fp16
    hgemm<2, 128, 64, 512><<<dim3(1, SEQ / 128, BATCH * HEADS), blk>>>(
        attnh, vT, nullptr, avh);

    // 5) output projection + bias -> fp32
    hgemm<1, 128, 128, 1024><<<dim3(DMODEL / 128, NTOK / 128), blk>>>(
        avh, woutT, b_out, out);
}

// round 12
// speedup vs baseline: 1.2441x; 1.2441x over previous
#include <cuda_runtime.h>
#include <cuda_fp16.h>
#include <stdint.h>
#include <math.h>

#define HEADS 16
#define DH    64
#define BATCH 8
#define SEQ   512
#define DMODEL 1024
#define INNER 1024            // HEADS*DH
#define QKV_N 3072            // 3*INNER
#define NTOK  4096            // BATCH*SEQ

// Scratch (device globals: allocation-free, graph-capture safe)
__device__ __half g_xh[(size_t)NTOK * DMODEL];               // 8 MB
__device__ __half g_qkvh[(size_t)NTOK * QKV_N];              // 24 MB
__device__ float  g_dots[(size_t)BATCH * HEADS * SEQ * SEQ]; // 128 MB
__device__ __half g_attnh[(size_t)BATCH * HEADS * SEQ * SEQ];// 64 MB
__device__ __half g_avh[(size_t)NTOK * INNER];               // 8 MB
__device__ __half g_wqkvT[(size_t)QKV_N * DMODEL];           // 6 MB [n][k]
__device__ __half g_woutT[(size_t)DMODEL * INNER];           // 2 MB [n][k]
__device__ __half g_vT[(size_t)BATCH * HEADS * DH * SEQ];    // 8 MB [b][h][d][j]

// ---------------------------------------------------------------------------
__device__ __forceinline__ void mma16(float* c, const uint32_t* a, const uint32_t* b) {
    asm volatile(
        "mma.sync.aligned.m16n8k16.row.col.f32.f16.f16.f32 "
        "{%0,%1,%2,%3}, {%4,%5,%6,%7}, {%8,%9}, {%0,%1,%2,%3};"
        : "+f"(c[0]), "+f"(c[1]), "+f"(c[2]), "+f"(c[3])
        : "r"(a[0]), "r"(a[1]), "r"(a[2]), "r"(a[3]),
          "r"(b[0]), "r"(b[1]));
}

__device__ __forceinline__ void ldsm_x4(uint32_t* r, const __half* p) {
    uint32_t addr = (uint32_t)__cvta_generic_to_shared(p);
    asm volatile(
        "ldmatrix.sync.aligned.m8n8.x4.shared.b16 {%0,%1,%2,%3}, [%4];"
        : "=r"(r[0]), "=r"(r[1]), "=r"(r[2]), "=r"(r[3]) : "r"(addr));
}

__device__ __forceinline__ void cp16(uint32_t smem_dst, const void* gsrc) {
    asm volatile("cp.async.cg.shared.global [%0], [%1], 16;"
                 :: "r"(smem_dst), "l"(gsrc));
}

// ---------------------------------------------------------------------------
// Prep kernels
// ---------------------------------------------------------------------------
__global__ void __launch_bounds__(256) x_cvt(
    const float* __restrict__ in, __half* __restrict__ out)
{
    size_t i = ((size_t)blockIdx.x * 256 + threadIdx.x) * 8;
    float4 a = *reinterpret_cast<const float4*>(in + i);
    float4 b = *reinterpret_cast<const float4*>(in + i + 4);
    __half2 h0 = __floats2half2_rn(a.x, a.y);
    __half2 h1 = __floats2half2_rn(a.z, a.w);
    __half2 h2 = __floats2half2_rn(b.x, b.y);
    __half2 h3 = __floats2half2_rn(b.z, b.w);
    uint4 u;
    u.x = *reinterpret_cast<uint32_t*>(&h0);
    u.y = *reinterpret_cast<uint32_t*>(&h1);
    u.z = *reinterpret_cast<uint32_t*>(&h2);
    u.w = *reinterpret_cast<uint32_t*>(&h3);
    *reinterpret_cast<uint4*>(out + i) = u;
}

__global__ void __launch_bounds__(256) transpose_cvt(
    const float* __restrict__ in, __half* __restrict__ out, int K, int N)
{
    __shared__ float tile[32][33];
    const int k0 = blockIdx.y * 32, n0 = blockIdx.x * 32;
    const int tx = threadIdx.x & 31, ty = threadIdx.x >> 5;
    #pragma unroll
    for (int t = 0; t < 4; t++)
        tile[ty + t * 8][tx] = in[(size_t)(k0 + ty + t * 8) * N + n0 + tx];
    __syncthreads();
    #pragma unroll
    for (int t = 0; t < 4; t++)
        out[(size_t)(n0 + ty + t * 8) * K + k0 + tx] =
            __float2half_rn(tile[tx][ty + t * 8]);
}

__global__ void __launch_bounds__(256) v_transpose(
    const __half* __restrict__ qkvh, __half* __restrict__ vT)
{
    __shared__ __half tile[32][34];
    const int bh = blockIdx.z, b = bh >> 4, h = bh & 15;
    const int j0 = blockIdx.x * 32, d0 = blockIdx.y * 32;
    const int tx = threadIdx.x & 31, ty = threadIdx.x >> 5;
    const __half* src = qkvh + (size_t)b * SEQ * QKV_N + 2 * INNER + h * DH;
    #pragma unroll
    for (int t = 0; t < 4; t++)
        tile[ty + t * 8][tx] = src[(size_t)(j0 + ty + t * 8) * QKV_N + d0 + tx];
    __syncthreads();
    __half* dst = vT + (size_t)bh * DH * SEQ;
    #pragma unroll
    for (int t = 0; t < 4; t++)
        dst[(size_t)(d0 + ty + t * 8) * SEQ + j0 + tx] = tile[tx][ty + t * 8];
}

// ---------------------------------------------------------------------------
// fp16 tensor-core GEMM: cp.async 3-stage pipeline + ldmatrix fragments.
// BN=64 warp tile (acc=32 regs) -> ~72 regs natural -> 3 CTAs/SM WITHOUT spill.
// MODE 0: QKV   MODE 1: OUT (+bias)   MODE 2: AV (per bh)   MODE 3: DOTS
// ---------------------------------------------------------------------------
template<int MODE, int BM, int BN, int KTOT>
__global__ void __launch_bounds__(256, 3) hgemm(
    const __half* __restrict__ gA, const __half* __restrict__ gB,
    const float* __restrict__ bias, void* __restrict__ gC)
{
    constexpr bool CHALF = (MODE == 0 || MODE == 2);
    constexpr int MI = BM / 64;
    constexpr int NP = BN / 32;
    constexpr int LK = 40;
    constexpr int S  = 3;
    constexpr int T  = KTOT / 32;
    constexpr int NLDA = BM / 64;
    constexpr int NLDB = BN / 64;

    __shared__ __align__(16) __half sA[S][BM * LK];
    __shared__ __align__(16) __half sB[S][BN * LK];

    const int tid  = threadIdx.x;
    const int row0 = blockIdx.y * BM;
    const int col0 = blockIdx.x * BN;

    const __half* A;
    const __half* B;
    float*  Cf = nullptr;
    __half* Ch = nullptr;
    int lda, ldb, ldc;
    float alpha = 1.0f;

    if (MODE == 0) {
        A = gA; lda = DMODEL; B = gB; ldb = DMODEL;
        Ch = (__half*)gC; ldc = QKV_N;
    } else if (MODE == 1) {
        A = gA; lda = DMODEL; B = gB; ldb = DMODEL;
        Cf = (float*)gC; ldc = DMODEL;
    } else if (MODE == 2) {
        const int bh = blockIdx.z, b = bh >> 4, h = bh & 15;
        A = gA + (size_t)bh * SEQ * SEQ;            lda = SEQ;
        B = gB + (size_t)bh * DH * SEQ;             ldb = SEQ;
        Ch = (__half*)gC + (size_t)b * SEQ * INNER + (size_t)h * DH; ldc = INNER;
    } else {
        const int bh = blockIdx.z, b = bh >> 4, h = bh & 15;
        A = gA + (size_t)b * SEQ * QKV_N + (size_t)h * DH;          lda = QKV_N;
        B = gB + (size_t)b * SEQ * QKV_N + INNER + (size_t)h * DH;  ldb = QKV_N;
        Cf = (float*)gC + (size_t)bh * SEQ * SEQ;                   ldc = SEQ;
        alpha = 0.125f;
    }

    const int warp = tid >> 5, lane = tid & 31;
    const int wm = warp >> 1, wn = warp & 1;
    const int g = lane >> 2, t4 = lane & 3;
    const int lmRow = lane & 15;
    const int lmK8  = (lane >> 4) * 8;

    const int hR = tid >> 2;
    const int hC = tid & 3;

    const uint32_t sA0 = (uint32_t)__cvta_generic_to_shared(&sA[0][0]);
    const uint32_t sB0 = (uint32_t)__cvta_generic_to_shared(&sB[0][0]);

    auto cpStage = [&](int kt, int st) {
        const int k0 = kt * 32;
        #pragma unroll
        for (int p = 0; p < NLDA; p++) {
            int r = hR + p * 64;
            cp16(sA0 + (uint32_t)((st * BM + r) * LK + hC * 8) * 2,
                 &A[(size_t)(row0 + r) * lda + k0 + hC * 8]);
        }
        #pragma unroll
        for (int p = 0; p < NLDB; p++) {
            int r = hR + p * 64;
            cp16(sB0 + (uint32_t)((st * BN + r) * LK + hC * 8) * 2,
                 &B[(size_t)(col0 + r) * ldb + k0 + hC * 8]);
        }
    };

    float acc[MI][NP * 2][4] = {};

    #pragma unroll
    for (int s = 0; s < S - 1; s++) {
        if (s < T) cpStage(s, s);
        asm volatile("cp.async.commit_group;");
    }

    for (int t = 0; t < T; t++) {
        asm volatile("cp.async.wait_group 1;");
        __syncthreads();

        const int nt = t + S - 1;
        if (nt < T) cpStage(nt, nt % S);
        asm volatile("cp.async.commit_group;");

        const __half* cA = sA[t % S];
        const __half* cB = sB[t % S];

        #pragma unroll
        for (int kk = 0; kk < 2; kk++) {
            const int kc = kk * 16 + lmK8;
            uint32_t af[MI][4];
            #pragma unroll
            for (int mi = 0; mi < MI; mi++) {
                int r = wm * (BM / 4) + mi * 16 + lmRow;
                ldsm_x4(af[mi], &cA[r * LK + kc]);
            }
            uint32_t bfp[NP][4];
            #pragma unroll
            for (int p = 0; p < NP; p++) {
                int c = wn * (BN / 2) + p * 16 + lmRow;
                ldsm_x4(bfp[p], &cB[c * LK + kc]);
            }
            #pragma unroll
            for (int mi = 0; mi < MI; mi++)
                #pragma unroll
                for (int p = 0; p < NP; p++) {
                    uint32_t b0[2] = { bfp[p][0], bfp[p][2] };
                    uint32_t b1[2] = { bfp[p][1], bfp[p][3] };
                    mma16(acc[mi][2 * p],     af[mi], b0);
                    mma16(acc[mi][2 * p + 1], af[mi], b1);
                }
        }
    }

    #pragma unroll
    for (int mi = 0; mi < MI; mi++) {
        int r = row0 + wm * (BM / 4) + mi * 16 + g;
        #pragma unroll
        for (int ni = 0; ni < NP * 2; ni++) {
            int c = col0 + wn * (BN / 2) + (ni >> 1) * 16 + (ni & 1) * 8 + 2 * t4;
            float* a = acc[mi][ni];
            if (CHALF) {
                __half2 hv0 = __floats2half2_rn(a[0], a[1]);
                __half2 hv1 = __floats2half2_rn(a[2], a[3]);
                *reinterpret_cast<__half2*>(&Ch[(size_t)r * ldc + c]) = hv0;
                *reinterpret_cast<__half2*>(&Ch[(size_t)(r + 8) * ldc + c]) = hv1;
            } else {
                float b0 = 0.f, b1 = 0.f;
                if (MODE == 1) { b0 = bias[c]; b1 = bias[c + 1]; }
                float2 v0, v1;
                v0.x = a[0] * alpha + b0; v0.y = a[1] * alpha + b1;
                v1.x = a[2] * alpha + b0; v1.y = a[3] * alpha + b1;
                *reinterpret_cast<float2*>(&Cf[(size_t)r * ldc + c]) = v0;
                *reinterpret_cast<float2*>(&Cf[(size_t)(r + 8) * ldc + c]) = v1;
            }
        }
    }
}

// ---------------------------------------------------------------------------
// Fused softmax + head-mix + LayerNorm (proven R7 version).
// ---------------------------------------------------------------------------
__global__ void __launch_bounds__(512) softmax_mix_ln_kernel(
    const float* __restrict__ dots, __half* __restrict__ attnh,
    const float* __restrict__ W,
    const float* __restrict__ gamma, const float* __restrict__ beta)
{
    const int bi = blockIdx.x;
    const int b  = bi >> 9;
    const int i  = bi & 511;

    __shared__ float sc[HEADS][SEQ];
    __shared__ float wmat[HEADS][HEADS];
    __shared__ float sg[HEADS], sb[HEADS];

    const int tid = threadIdx.x;
    if (tid < 256) wmat[tid >> 4][tid & 15] = W[tid];
    if (tid < HEADS) { sg[tid] = gamma[tid]; sb[tid] = beta[tid]; }

    #pragma unroll
    for (int t = 0; t < 4; t++) {
        int idx = tid + t * 512;
        int h   = idx >> 7;
        int j4  = idx & 127;
        float4 v = *reinterpret_cast<const float4*>(
            &dots[((size_t)(b * HEADS + h) * SEQ + i) * SEQ + j4 * 4]);
        *reinterpret_cast<float4*>(&sc[h][j4 * 4]) = v;
    }
    __syncthreads();

    const int h = tid >> 5, lane = tid & 31;
    {
        float mx = -1e30f;
        #pragma unroll
        for (int t = 0; t < 16; t++) mx = fmaxf(mx, sc[h][lane + t * 32]);
        #pragma unroll
        for (int o = 16; o > 0; o >>= 1)
            mx = fmaxf(mx, __shfl_xor_sync(0xffffffffu, mx, o));
        float s = 0.f;
        #pragma unroll
        for (int t = 0; t < 16; t++) {
            float e = __expf(sc[h][lane + t * 32] - mx);
            sc[h][lane + t * 32] = e;
            s += e;
        }
        #pragma unroll
        for (int o = 16; o > 0; o >>= 1)
            s += __shfl_xor_sync(0xffffffffu, s, o);
        float inv = 1.f / s;
        #pragma unroll
        for (int t = 0; t < 16; t++) sc[h][lane + t * 32] *= inv;
    }
    __syncthreads();

    {
        const int j = tid;
        float a[HEADS];
        #pragma unroll
        for (int hh = 0; hh < HEADS; hh++) a[hh] = sc[hh][j];
        float mixed[HEADS];
        #pragma unroll
        for (int gg = 0; gg < HEADS; gg++) {
            float s = 0.f;
            #pragma unroll
            for (int hh = 0; hh < HEADS; hh++) s = fmaf(a[hh], wmat[hh][gg], s);
            mixed[gg] = s;
        }
        float mean = 0.f;
        #pragma unroll
        for (int gg = 0; gg < HEADS; gg++) mean += mixed[gg];
        mean *= (1.f / HEADS);
        float var = 0.f;
        #pragma unroll
        for (int gg = 0; gg < HEADS; gg++) {
            float d = mixed[gg] - mean;
            var = fmaf(d, d, var);
        }
        var *= (1.f / HEADS);
        float inv = rsqrtf(var + 1e-3f);
        #pragma unroll
        for (int gg = 0; gg < HEADS; gg++) {
            float y = (mixed[gg] - mean) * inv * sg[gg] + sb[gg];
            attnh[((size_t)(b * HEADS + gg) * SEQ + i) * SEQ + j] =
                __float2half_rn(y);
        }
    }
}

// ---------------------------------------------------------------------------
extern "C" void kernel_launch(void* const* d_in, const int* in_sizes, int n_in,
                              void* d_out, int out_size)
{
    const float* x        = (const float*)d_in[0];
    const float* w_qkv    = (const float*)d_in[1];
    const float* reattn_w = (const float*)d_in[2];
    const float* ln_gamma = (const float*)d_in[3];
    const float* ln_beta  = (const float*)d_in[4];
    const float* w_out    = (const float*)d_in[5];
    const float* b_out    = (const float*)d_in[6];
    float* out = (float*)d_out;

    __half *xh = nullptr, *qkvh = nullptr, *attnh = nullptr, *avh = nullptr;
    __half *wqkvT = nullptr, *woutT = nullptr, *vT = nullptr;
    float *dots = nullptr;
    cudaGetSymbolAddress((void**)&xh,    g_xh);
    cudaGetSymbolAddress((void**)&qkvh,  g_qkvh);
    cudaGetSymbolAddress((void**)&dots,  g_dots);
    cudaGetSymbolAddress((void**)&attnh, g_attnh);
    cudaGetSymbolAddress((void**)&avh,   g_avh);
    cudaGetSymbolAddress((void**)&wqkvT, g_wqkvT);
    cudaGetSymbolAddress((void**)&woutT, g_woutT);
    cudaGetSymbolAddress((void**)&vT,    g_vT);

    dim3 blk(256);

    // 0) prep
    x_cvt<<<(NTOK * DMODEL) / (256 * 8), blk>>>(x, xh);
    transpose_cvt<<<dim3(QKV_N / 32, DMODEL / 32), blk>>>(w_qkv, wqkvT, DMODEL, QKV_N);
    transpose_cvt<<<dim3(DMODEL / 32, DMODEL / 32), blk>>>(w_out, woutT, DMODEL, DMODEL);

    // 1) QKV projection -> fp16  (BN=64)
    hgemm<0, 128, 64, 1024><<<dim3(QKV_N / 64, NTOK / 128), blk>>>(
        xh, wqkvT, nullptr, qkvh);

    // 1b) V transpose
    v_transpose<<<dim3(SEQ / 32, DH / 32, BATCH * HEADS), blk>>>(qkvh, vT);

    // 2) dots -> fp32  (BN=64)
    hgemm<3, 128, 64, 64><<<dim3(SEQ / 64, SEQ / 128, BATCH * HEADS), blk>>>(
        qkvh, qkvh, nullptr, dots);

    // 3) fused softmax + head mix + LayerNorm -> fp16
    softmax_mix_ln_kernel<<<BATCH * SEQ, 512>>>(dots, attnh, reattn_w, ln_gamma, ln_beta);

    // 4) AV -> fp16  (BN=64)
    hgemm<2, 128, 64, 512><<<dim3(1, SEQ / 128, BATCH * HEADS), blk>>>(
        attnh, vT, nullptr, avh);

    // 5) output projection + bias -> fp32  (BN=64)
    hgemm<1, 128, 64, 1024><<<dim3(DMODEL / 64, NTOK / 128), blk>>>(
        avh, woutT, b_out, out);
}

// round 13
// speedup vs baseline: 1.2654x; 1.0171x over previous
#include <cuda_runtime.h>
#include <cuda_fp16.h>
#include <stdint.h>
#include <math.h>

#define HEADS 16
#define DH    64
#define BATCH 8
#define SEQ   512
#define DMODEL 1024
#define INNER 1024            // HEADS*DH
#define QKV_N 3072            // 3*INNER
#define NTOK  4096            // BATCH*SEQ

// Scratch (device globals: allocation-free, graph-capture safe)
__device__ __half g_xh[(size_t)NTOK * DMODEL];               // 8 MB
__device__ __half g_qkvh[(size_t)NTOK * QKV_N];              // 24 MB
__device__ float  g_dots[(size_t)BATCH * HEADS * SEQ * SEQ]; // 128 MB
__device__ __half g_attnh[(size_t)BATCH * HEADS * SEQ * SEQ];// 64 MB
__device__ __half g_avh[(size_t)NTOK * INNER];               // 8 MB
__device__ __half g_wqkvT[(size_t)QKV_N * DMODEL];           // 6 MB [n][k]
__device__ __half g_woutT[(size_t)DMODEL * INNER];           // 2 MB [n][k]
__device__ __half g_vT[(size_t)BATCH * HEADS * DH * SEQ];    // 8 MB [b][h][d][j]

// ---------------------------------------------------------------------------
__device__ __forceinline__ void mma16(float* c, const uint32_t* a, const uint32_t* b) {
    asm volatile(
        "mma.sync.aligned.m16n8k16.row.col.f32.f16.f16.f32 "
        "{%0,%1,%2,%3}, {%4,%5,%6,%7}, {%8,%9}, {%0,%1,%2,%3};"
        : "+f"(c[0]), "+f"(c[1]), "+f"(c[2]), "+f"(c[3])
        : "r"(a[0]), "r"(a[1]), "r"(a[2]), "r"(a[3]),
          "r"(b[0]), "r"(b[1]));
}

__device__ __forceinline__ void ldsm_x4(uint32_t* r, const __half* p) {
    uint32_t addr = (uint32_t)__cvta_generic_to_shared(p);
    asm volatile(
        "ldmatrix.sync.aligned.m8n8.x4.shared.b16 {%0,%1,%2,%3}, [%4];"
        : "=r"(r[0]), "=r"(r[1]), "=r"(r[2]), "=r"(r[3]) : "r"(addr));
}

__device__ __forceinline__ void cp16(uint32_t smem_dst, const void* gsrc) {
    asm volatile("cp.async.cg.shared.global [%0], [%1], 16;"
                 :: "r"(smem_dst), "l"(gsrc));
}

// ---------------------------------------------------------------------------
// Prep kernels
// ---------------------------------------------------------------------------
__global__ void __launch_bounds__(256) x_cvt(
    const float* __restrict__ in, __half* __restrict__ out)
{
    size_t i = ((size_t)blockIdx.x * 256 + threadIdx.x) * 8;
    float4 a = *reinterpret_cast<const float4*>(in + i);
    float4 b = *reinterpret_cast<const float4*>(in + i + 4);
    __half2 h0 = __floats2half2_rn(a.x, a.y);
    __half2 h1 = __floats2half2_rn(a.z, a.w);
    __half2 h2 = __floats2half2_rn(b.x, b.y);
    __half2 h3 = __floats2half2_rn(b.z, b.w);
    uint4 u;
    u.x = *reinterpret_cast<uint32_t*>(&h0);
    u.y = *reinterpret_cast<uint32_t*>(&h1);
    u.z = *reinterpret_cast<uint32_t*>(&h2);
    u.w = *reinterpret_cast<uint32_t*>(&h3);
    *reinterpret_cast<uint4*>(out + i) = u;
}

__global__ void __launch_bounds__(256) transpose_cvt(
    const float* __restrict__ in, __half* __restrict__ out, int K, int N)
{
    __shared__ float tile[32][33];
    const int k0 = blockIdx.y * 32, n0 = blockIdx.x * 32;
    const int tx = threadIdx.x & 31, ty = threadIdx.x >> 5;
    #pragma unroll
    for (int t = 0; t < 4; t++)
        tile[ty + t * 8][tx] = in[(size_t)(k0 + ty + t * 8) * N + n0 + tx];
    __syncthreads();
    #pragma unroll
    for (int t = 0; t < 4; t++)
        out[(size_t)(n0 + ty + t * 8) * K + k0 + tx] =
            __float2half_rn(tile[tx][ty + t * 8]);
}

__global__ void __launch_bounds__(256) v_transpose(
    const __half* __restrict__ qkvh, __half* __restrict__ vT)
{
    __shared__ __half tile[32][34];
    const int bh = blockIdx.z, b = bh >> 4, h = bh & 15;
    const int j0 = blockIdx.x * 32, d0 = blockIdx.y * 32;
    const int tx = threadIdx.x & 31, ty = threadIdx.x >> 5;
    const __half* src = qkvh + (size_t)b * SEQ * QKV_N + 2 * INNER + h * DH;
    #pragma unroll
    for (int t = 0; t < 4; t++)
        tile[ty + t * 8][tx] = src[(size_t)(j0 + ty + t * 8) * QKV_N + d0 + tx];
    __syncthreads();
    __half* dst = vT + (size_t)bh * DH * SEQ;
    #pragma unroll
    for (int t = 0; t < 4; t++)
        dst[(size_t)(d0 + ty + t * 8) * SEQ + j0 + tx] = tile[tx][ty + t * 8];
}

// ---------------------------------------------------------------------------
// fp16 tensor-core GEMM: cp.async 2-stage pipeline, BK=64 per stage
// (4 k16 steps per __syncthreads), ldmatrix fragments, LK=72 (conflict-free:
// per-phase row offsets r*36 mod 32 words hit 8 distinct 16B groups).
// BN=64 warp tile -> ~80 regs -> 3 CTAs/SM without spill.
// MODE 0: QKV   MODE 1: OUT (+bias)   MODE 2: AV (per bh)   MODE 3: DOTS
// ---------------------------------------------------------------------------
template<int MODE, int BM, int BN, int KTOT>
__global__ void __launch_bounds__(256, 3) hgemm(
    const __half* __restrict__ gA, const __half* __restrict__ gB,
    const float* __restrict__ bias, void* __restrict__ gC)
{
    constexpr bool CHALF = (MODE == 0 || MODE == 2);
    constexpr int MI = BM / 64;
    constexpr int NP = BN / 32;
    constexpr int LK = 72;               // padded stride for BK=64
    constexpr int S  = 2;
    constexpr int BK = 64;
    constexpr int T  = KTOT / BK;
    constexpr int NLDA = BM / 32;        // cp16 per thread (A: BM*8/256)
    constexpr int NLDB = BN / 32;

    __shared__ __align__(16) __half sA[S][BM * LK];
    __shared__ __align__(16) __half sB[S][BN * LK];

    const int tid  = threadIdx.x;
    const int row0 = blockIdx.y * BM;
    const int col0 = blockIdx.x * BN;

    const __half* A;
    const __half* B;
    float*  Cf = nullptr;
    __half* Ch = nullptr;
    int lda, ldb, ldc;
    float alpha = 1.0f;

    if (MODE == 0) {
        A = gA; lda = DMODEL; B = gB; ldb = DMODEL;
        Ch = (__half*)gC; ldc = QKV_N;
    } else if (MODE == 1) {
        A = gA; lda = DMODEL; B = gB; ldb = DMODEL;
        Cf = (float*)gC; ldc = DMODEL;
    } else if (MODE == 2) {
        const int bh = blockIdx.z, b = bh >> 4, h = bh & 15;
        A = gA + (size_t)bh * SEQ * SEQ;            lda = SEQ;
        B = gB + (size_t)bh * DH * SEQ;             ldb = SEQ;
        Ch = (__half*)gC + (size_t)b * SEQ * INNER + (size_t)h * DH; ldc = INNER;
    } else {
        const int bh = blockIdx.z, b = bh >> 4, h = bh & 15;
        A = gA + (size_t)b * SEQ * QKV_N + (size_t)h * DH;          lda = QKV_N;
        B = gB + (size_t)b * SEQ * QKV_N + INNER + (size_t)h * DH;  ldb = QKV_N;
        Cf = (float*)gC + (size_t)bh * SEQ * SEQ;                   ldc = SEQ;
        alpha = 0.125f;
    }

    const int warp = tid >> 5, lane = tid & 31;
    const int wm = warp >> 1, wn = warp & 1;
    const int g = lane >> 2, t4 = lane & 3;
    const int lmRow = lane & 15;
    const int lmK8  = (lane >> 4) * 8;

    const int cR = tid >> 3;             // cp row base (0..31)
    const int cC = tid & 7;              // 16B chunk within 128B row

    const uint32_t sA0 = (uint32_t)__cvta_generic_to_shared(&sA[0][0]);
    const uint32_t sB0 = (uint32_t)__cvta_generic_to_shared(&sB[0][0]);

    auto cpStage = [&](int kt, int st) {
        const int k0 = kt * BK;
        #pragma unroll
        for (int p = 0; p < NLDA; p++) {
            int r = cR + p * 32;
            cp16(sA0 + (uint32_t)((st * BM + r) * LK + cC * 8) * 2,
                 &A[(size_t)(row0 + r) * lda + k0 + cC * 8]);
        }
        #pragma unroll
        for (int p = 0; p < NLDB; p++) {
            int r = cR + p * 32;
            cp16(sB0 + (uint32_t)((st * BN + r) * LK + cC * 8) * 2,
                 &B[(size_t)(col0 + r) * ldb + k0 + cC * 8]);
        }
    };

    float acc[MI][NP * 2][4] = {};

    cpStage(0, 0);
    asm volatile("cp.async.commit_group;");

    for (int t = 0; t < T; t++) {
        asm volatile("cp.async.wait_group 0;");
        __syncthreads();

        if (t + 1 < T) cpStage(t + 1, (t + 1) & 1);
        asm volatile("cp.async.commit_group;");

        const __half* cA = sA[t & 1];
        const __half* cB = sB[t & 1];

        #pragma unroll
        for (int kk = 0; kk < 4; kk++) {
            const int kc = kk * 16 + lmK8;
            uint32_t af[MI][4];
            #pragma unroll
            for (int mi = 0; mi < MI; mi++) {
                int r = wm * (BM / 4) + mi * 16 + lmRow;
                ldsm_x4(af[mi], &cA[r * LK + kc]);
            }
            uint32_t bfp[NP][4];
            #pragma unroll
            for (int p = 0; p < NP; p++) {
                int c = wn * (BN / 2) + p * 16 + lmRow;
                ldsm_x4(bfp[p], &cB[c * LK + kc]);
            }
            #pragma unroll
            for (int mi = 0; mi < MI; mi++)
                #pragma unroll
                for (int p = 0; p < NP; p++) {
                    uint32_t b0[2] = { bfp[p][0], bfp[p][2] };
                    uint32_t b1[2] = { bfp[p][1], bfp[p][3] };
                    mma16(acc[mi][2 * p],     af[mi], b0);
                    mma16(acc[mi][2 * p + 1], af[mi], b1);
                }
        }
    }

    #pragma unroll
    for (int mi = 0; mi < MI; mi++) {
        int r = row0 + wm * (BM / 4) + mi * 16 + g;
        #pragma unroll
        for (int ni = 0; ni < NP * 2; ni++) {
            int c = col0 + wn * (BN / 2) + (ni >> 1) * 16 + (ni & 1) * 8 + 2 * t4;
            float* a = acc[mi][ni];
            if (CHALF) {
                __half2 hv0 = __floats2half2_rn(a[0], a[1]);
                __half2 hv1 = __floats2half2_rn(a[2], a[3]);
                *reinterpret_cast<__half2*>(&Ch[(size_t)r * ldc + c]) = hv0;
                *reinterpret_cast<__half2*>(&Ch[(size_t)(r + 8) * ldc + c]) = hv1;
            } else {
                float b0 = 0.f, b1 = 0.f;
                if (MODE == 1) { b0 = bias[c]; b1 = bias[c + 1]; }
                float2 v0, v1;
                v0.x = a[0] * alpha + b0; v0.y = a[1] * alpha + b1;
                v1.x = a[2] * alpha + b0; v1.y = a[3] * alpha + b1;
                *reinterpret_cast<float2*>(&Cf[(size_t)r * ldc + c]) = v0;
                *reinterpret_cast<float2*>(&Cf[(size_t)(r + 8) * ldc + c]) = v1;
            }
        }
    }
}

// ---------------------------------------------------------------------------
// Fused softmax + head-mix + LayerNorm (proven R7 version).
// ---------------------------------------------------------------------------
__global__ void __launch_bounds__(512) softmax_mix_ln_kernel(
    const float* __restrict__ dots, __half* __restrict__ attnh,
    const float* __restrict__ W,
    const float* __restrict__ gamma, const float* __restrict__ beta)
{
    const int bi = blockIdx.x;
    const int b  = bi >> 9;
    const int i  = bi & 511;

    __shared__ float sc[HEADS][SEQ];
    __shared__ float wmat[HEADS][HEADS];
    __shared__ float sg[HEADS], sb[HEADS];

    const int tid = threadIdx.x;
    if (tid < 256) wmat[tid >> 4][tid & 15] = W[tid];
    if (tid < HEADS) { sg[tid] = gamma[tid]; sb[tid] = beta[tid]; }

    #pragma unroll
    for (int t = 0; t < 4; t++) {
        int idx = tid + t * 512;
        int h   = idx >> 7;
        int j4  = idx & 127;
        float4 v = *reinterpret_cast<const float4*>(
            &dots[((size_t)(b * HEADS + h) * SEQ + i) * SEQ + j4 * 4]);
        *reinterpret_cast<float4*>(&sc[h][j4 * 4]) = v;
    }
    __syncthreads();

    const int h = tid >> 5, lane = tid & 31;
    {
        float mx = -1e30f;
        #pragma unroll
        for (int t = 0; t < 16; t++) mx = fmaxf(mx, sc[h][lane + t * 32]);
        #pragma unroll
        for (int o = 16; o > 0; o >>= 1)
            mx = fmaxf(mx, __shfl_xor_sync(0xffffffffu, mx, o));
        float s = 0.f;
        #pragma unroll
        for (int t = 0; t < 16; t++) {
            float e = __expf(sc[h][lane + t * 32] - mx);
            sc[h][lane + t * 32] = e;
            s += e;
        }
        #pragma unroll
        for (int o = 16; o > 0; o >>= 1)
            s += __shfl_xor_sync(0xffffffffu, s, o);
        float inv = 1.f / s;
        #pragma unroll
        for (int t = 0; t < 16; t++) sc[h][lane + t * 32] *= inv;
    }
    __syncthreads();

    {
        const int j = tid;
        float a[HEADS];
        #pragma unroll
        for (int hh = 0; hh < HEADS; hh++) a[hh] = sc[hh][j];
        float mixed[HEADS];
        #pragma unroll
        for (int gg = 0; gg < HEADS; gg++) {
            float s = 0.f;
            #pragma unroll
            for (int hh = 0; hh < HEADS; hh++) s = fmaf(a[hh], wmat[hh][gg], s);
            mixed[gg] = s;
        }
        float mean = 0.f;
        #pragma unroll
        for (int gg = 0; gg < HEADS; gg++) mean += mixed[gg];
        mean *= (1.f / HEADS);
        float var = 0.f;
        #pragma unroll
        for (int gg = 0; gg < HEADS; gg++) {
            float d = mixed[gg] - mean;
            var = fmaf(d, d, var);
        }
        var *= (1.f / HEADS);
        float inv = rsqrtf(var + 1e-3f);
        #pragma unroll
        for (int gg = 0; gg < HEADS; gg++) {
            float y = (mixed[gg] - mean) * inv * sg[gg] + sb[gg];
            attnh[((size_t)(b * HEADS + gg) * SEQ + i) * SEQ + j] =
                __float2half_rn(y);
        }
    }
}

// ---------------------------------------------------------------------------
extern "C" void kernel_launch(void* const* d_in, const int* in_sizes, int n_in,
                              void* d_out, int out_size)
{
    const float* x        = (const float*)d_in[0];
    const float* w_qkv    = (const float*)d_in[1];
    const float* reattn_w = (const float*)d_in[2];
    const float* ln_gamma = (const float*)d_in[3];
    const float* ln_beta  = (const float*)d_in[4];
    const float* w_out    = (const float*)d_in[5];
    const float* b_out    = (const float*)d_in[6];
    float* out = (float*)d_out;

    __half *xh = nullptr, *qkvh = nullptr, *attnh = nullptr, *avh = nullptr;
    __half *wqkvT = nullptr, *woutT = nullptr, *vT = nullptr;
    float *dots = nullptr;
    cudaGetSymbolAddress((void**)&xh,    g_xh);
    cudaGetSymbolAddress((void**)&qkvh,  g_qkvh);
    cudaGetSymbolAddress((void**)&dots,  g_dots);
    cudaGetSymbolAddress((void**)&attnh, g_attnh);
    cudaGetSymbolAddress((void**)&avh,   g_avh);
    cudaGetSymbolAddress((void**)&wqkvT, g_wqkvT);
    cudaGetSymbolAddress((void**)&woutT, g_woutT);
    cudaGetSymbolAddress((void**)&vT,    g_vT);

    dim3 blk(256);

    // 0) prep
    x_cvt<<<(NTOK * DMODEL) / (256 * 8), blk>>>(x, xh);
    transpose_cvt<<<dim3(QKV_N / 32, DMODEL / 32), blk>>>(w_qkv, wqkvT, DMODEL, QKV_N);
    transpose_cvt<<<dim3(DMODEL / 32, DMODEL / 32), blk>>>(w_out, woutT, DMODEL, DMODEL);

    // 1) QKV projection -> fp16
    hgemm<0, 128, 64, 1024><<<dim3(QKV_N / 64, NTOK / 128), blk>>>(
        xh, wqkvT, nullptr, qkvh);

    // 1b) V transpose
    v_transpose<<<dim3(SEQ / 32, DH / 32, BATCH * HEADS), blk>>>(qkvh, vT);

    // 2) dots -> fp32
    hgemm<3, 128, 64, 64><<<dim3(SEQ / 64, SEQ / 128, BATCH * HEADS), blk>>>(
        qkvh, qkvh, nullptr, dots);

    // 3) fused softmax + head mix + LayerNorm -> fp16
    softmax_mix_ln_kernel<<<BATCH * SEQ, 512>>>(dots, attnh, reattn_w, ln_gamma, ln_beta);

    // 4) AV -> fp16
    hgemm<2, 128, 64, 512><<<dim3(1, SEQ / 128, BATCH * HEADS), blk>>>(
        attnh, vT, nullptr, avh);

    // 5) output projection + bias -> fp32
    hgemm<1, 128, 64, 1024><<<dim3(DMODEL / 64, NTOK / 128), blk>>>(
        avh, woutT, b_out, out);
}